// round 14
// baseline (speedup 1.0000x reference)
#include <cuda_runtime.h>
#include <cuda_fp16.h>
#include <cstdint>
#include <math.h>

#define V_NUM   100000
#define R_NUM   100000
#define NBRS    20
#define NCLS    10
#define DT_ROWS 200004
#define DT_OFF  100000
#define ROWH    160          // fused row: [K ch0-127 | CV 32] halfs = 320B

// ---------------- scratch tables (device globals) ---------------------------
__device__ __align__(16) __half g_tabQ_h[(size_t)V_NUM * 128];
__device__ __align__(16) __half g_tabFv [(size_t)V_NUM * ROWH];
__device__ __align__(16) __half g_tabFr [(size_t)R_NUM * ROWH];
__device__ __align__(16) __half g_tabFt [(size_t)DT_ROWS * ROWH];
__device__ __align__(16) float  g_E     [(size_t)DT_ROWS * 128]; // cos matrix
__device__ __align__(16) float  g_CVWv[128 * 128];   // (Wco(x)Wv) slices, rows 0-31 used
__device__ __align__(16) float  g_CVWr[128 * 128];
__device__ __align__(16) float  g_CVWt[128 * 128];
__device__ float g_qcb [128];
__device__ float g_cvb [32];
__device__ float g_bco [NCLS];
__device__ int   g_is64;
__device__ int   g_mask32;

// Fast fp32 cosine with FMA Cody-Waite reduction (no DP, fast-math-proof).
__device__ __forceinline__ float cosq(float x)
{
    float kf = rintf(x * 0.6366197723675814f);
    int   k  = (int)kf;
    float r  = fmaf(kf, -1.57079637050628662109375f, x);
    r        = fmaf(kf,  4.37113900018624283e-8f,    r);
    float r2 = r * r;
    float c = fmaf(r2, fmaf(r2, fmaf(r2, fmaf(r2, 2.47959626e-5f, -1.38888876e-3f),
                                      4.16666418e-2f), -4.99999970e-1f), 1.0f);
    float s = r * fmaf(r2, fmaf(r2, fmaf(r2, -1.95152959e-4f, 8.33216087e-3f),
                                 -1.66666546e-1f), 1.0f);
    int q = k & 3;
    float res = (q & 1) ? s : c;
    return ((q == 1) || (q == 2)) ? -res : res;
}

__device__ __forceinline__ uint32_t f2tf32(float f)
{
    uint32_t u;
    asm("cvt.rna.tf32.f32 %0, %1;" : "=r"(u) : "f"(f));
    return u;
}

__device__ __forceinline__ void mma8(float* d, const uint32_t* a, uint32_t b0, uint32_t b1)
{
    asm volatile(
        "mma.sync.aligned.m16n8k8.row.col.f32.tf32.tf32.f32 "
        "{%0,%1,%2,%3},{%4,%5,%6,%7},{%8,%9},{%0,%1,%2,%3};"
        : "+f"(d[0]), "+f"(d[1]), "+f"(d[2]), "+f"(d[3])
        : "r"(a[0]), "r"(a[1]), "r"(a[2]), "r"(a[3]), "r"(b0), "r"(b1));
}

// ---------------- dtype detects ----------------------------------------------
__global__ void tgn_detect_node(const int* __restrict__ node, int n_words)
{
    __shared__ int sOr[256];
    int t = threadIdx.x;
    int acc = 0;
    for (int i = 1 + 2 * t; i < n_words; i += 512) acc |= node[i];
    sOr[t] = acc;
    __syncthreads();
    for (int s = 128; s; s >>= 1) { if (t < s) sOr[t] |= sOr[t + s]; __syncthreads(); }
    if (t == 0) g_is64 = (sOr[0] == 0) ? 1 : 0;
}

__global__ void tgn_detect_mask(const unsigned char* __restrict__ m, int n_elems)
{
    __shared__ int sOr[256];
    int t = threadIdx.x;
    int acc = 0;
    for (int i = t; i < n_elems; i += 256)
        if (i & 3) acc |= m[i];
    sOr[t] = acc;
    __syncthreads();
    for (int s = 128; s; s >>= 1) { if (t < s) sOr[t] |= sOr[t + s]; __syncthreads(); }
    if (t == 0) g_mask32 = (sOr[0] == 0) ? 1 : 0;
}

// ---------------- prep: constants + classifier-folded CV weights -------------
__global__ void tgn_prep(const float* __restrict__ Wq, const float* __restrict__ bq,
                         const float* __restrict__ Wv, const float* __restrict__ bv,
                         const float* __restrict__ Wo, const float* __restrict__ bo,
                         const float* __restrict__ Wc, const float* __restrict__ bc,
                         const float* __restrict__ tb)
{
    __shared__ float sWco[NCLS][128];
    int t = threadIdx.x;  // 128 threads

    float acc = bq[t];
    for (int c = 0; c < 128; ++c) acc += Wq[t * 256 + 128 + c] * cosq(tb[c]);
    g_qcb[t] = acc;

    for (int c = 0; c < NCLS; ++c) {
        float s = 0.f;
        for (int m = 0; m < 128; ++m) s += Wc[c * 128 + m] * Wo[m * 128 + t];
        sWco[c][t] = s;
    }
    if (t < NCLS) {
        float s = bc[t];
        for (int m = 0; m < 128; ++m) s += Wc[t * 128 + m] * bo[m];
        g_bco[t] = s;
    }
    __syncthreads();

#pragma unroll
    for (int type = 0; type < 3; ++type) {
        float* dst = (type == 0) ? g_CVWv : (type == 1) ? g_CVWr : g_CVWt;
        int off = type * 128;
        for (int o = 0; o < NCLS; ++o) {
            float h0 = 0.f, h1 = 0.f;
            for (int c = 0; c < 64; ++c) {
                h0 += sWco[o][c]      * Wv[(c)      * 384 + off + t];
                h1 += sWco[o][c + 64] * Wv[(c + 64) * 384 + off + t];
            }
            dst[o * 128 + t]        = h0;
            dst[(16 + o) * 128 + t] = h1;
        }
        for (int o = NCLS; o < 16; ++o) {
            dst[o * 128 + t]        = 0.f;
            dst[(16 + o) * 128 + t] = 0.f;
        }
    }
    if (t < 32) {
        int head = t >> 4, o = t & 15;
        float val = 0.f;
        if (o < NCLS)
            for (int c = 0; c < 64; ++c)
                val += sWco[o][head * 64 + c] * bv[head * 64 + c];
        g_cvb[t] = val;
    }
}

// ---------------- cos matrix ---------------------------------------------------
__global__ void tgn_cosE(const float* __restrict__ tw, const float* __restrict__ tb)
{
    long idx = (long)blockIdx.x * 256 + threadIdx.x;
    long row = idx >> 5;
    if (row >= DT_ROWS) return;
    int  c4 = (int)(idx & 31) * 4;
    float dv = (float)(row - DT_OFF);
    float4 w = *reinterpret_cast<const float4*>(&tw[c4]);
    float4 b = *reinterpret_cast<const float4*>(&tb[c4]);
    float4 o;
    o.x = cosq(__fadd_rn(__fmul_rn(dv, w.x), b.x));
    o.y = cosq(__fadd_rn(__fmul_rn(dv, w.y), b.y));
    o.z = cosq(__fadd_rn(__fmul_rn(dv, w.z), b.z));
    o.w = cosq(__fadd_rn(__fmul_rn(dv, w.w), b.w));
    *reinterpret_cast<float4*>(&g_E[row * 128 + c4]) = o;
}

// ---------------- unified tf32 MMA table GEMM --------------------------------
// tab: 0 Q (ldc 128), 1 Fv, 2 Fr, 3 Ft (ldc 160). cofs selects K (0) / CV (128) part.
// wsel: 0 = external W pointer, 1/2/3 = g_CVWv/r/t. biasmode: 0 ext, 1 qcb, 2 cvb.
struct TSlice  { const float* W; const float* bias; int ldw; int tab; int cofs; int ncols; int biasmode; int wsel; };
struct TSlice3 { TSlice s[3]; };

__global__ __launch_bounds__(256)
void tgn_mma(const float* __restrict__ Ain, int M, TSlice3 P)
{
    __shared__ uint32_t As[128][36];
    __shared__ uint32_t Bs[128][36];
    TSlice sl = P.s[blockIdx.y];
    const float* A = Ain ? Ain : (const float*)g_E;
    const float* W = (sl.wsel == 1) ? g_CVWv : (sl.wsel == 2) ? g_CVWr
                   : (sl.wsel == 3) ? g_CVWt : sl.W;
    __half* C = (sl.tab == 0) ? g_tabQ_h : (sl.tab == 1) ? g_tabFv
              : (sl.tab == 2) ? g_tabFr  : g_tabFt;
    int ldc = (sl.tab == 0) ? 128 : ROWH;
    const float* bias = (sl.biasmode == 1) ? g_qcb : (sl.biasmode == 2) ? g_cvb : sl.bias;

    int m0   = blockIdx.x * 128;
    int tid  = threadIdx.x;
    int warp = tid >> 5, lane = tid & 31;
    int wm = warp >> 2, wn = warp & 3;
    int g  = lane >> 2, t4 = lane & 3;

    float acc[4][4][4];
#pragma unroll
    for (int a = 0; a < 4; ++a)
#pragma unroll
        for (int b = 0; b < 4; ++b)
#pragma unroll
            for (int d = 0; d < 4; ++d) acc[a][b][d] = 0.f;

    for (int kc = 0; kc < 128; kc += 32) {
        __syncthreads();
#pragma unroll
        for (int it = 0; it < 4; ++it) {
            int idx = tid + it * 256;
            int r   = idx >> 3;
            int c4  = (idx & 7) * 4;
            float4 av = make_float4(0.f, 0.f, 0.f, 0.f);
            if (m0 + r < M)
                av = *reinterpret_cast<const float4*>(&A[(size_t)(m0 + r) * 128 + kc + c4]);
            As[r][c4 + 0] = f2tf32(av.x); As[r][c4 + 1] = f2tf32(av.y);
            As[r][c4 + 2] = f2tf32(av.z); As[r][c4 + 3] = f2tf32(av.w);
            float4 bv = *reinterpret_cast<const float4*>(&W[(size_t)r * sl.ldw + kc + c4]);
            Bs[r][c4 + 0] = f2tf32(bv.x); Bs[r][c4 + 1] = f2tf32(bv.y);
            Bs[r][c4 + 2] = f2tf32(bv.z); Bs[r][c4 + 3] = f2tf32(bv.w);
        }
        __syncthreads();
#pragma unroll
        for (int ks = 0; ks < 4; ++ks) {
            int k0 = ks * 8;
            uint32_t af[4][4];
#pragma unroll
            for (int mt = 0; mt < 4; ++mt) {
                int rm = wm * 64 + mt * 16;
                af[mt][0] = As[rm + g    ][k0 + t4];
                af[mt][1] = As[rm + g + 8][k0 + t4];
                af[mt][2] = As[rm + g    ][k0 + t4 + 4];
                af[mt][3] = As[rm + g + 8][k0 + t4 + 4];
            }
#pragma unroll
            for (int nt = 0; nt < 4; ++nt) {
                int nb = wn * 32 + nt * 8;
                uint32_t b0 = Bs[nb + g][k0 + t4];
                uint32_t b1 = Bs[nb + g][k0 + t4 + 4];
#pragma unroll
                for (int mt = 0; mt < 4; ++mt)
                    mma8(acc[mt][nt], af[mt], b0, b1);
            }
        }
    }

#pragma unroll
    for (int nt = 0; nt < 4; ++nt) {
        int lc = wn * 32 + nt * 8 + 2 * t4;
        if (lc >= sl.ncols) continue;
        float b0v = bias ? bias[lc]     : 0.f;
        float b1v = bias ? bias[lc + 1] : 0.f;
#pragma unroll
        for (int mt = 0; mt < 4; ++mt) {
            int r0 = m0 + wm * 64 + mt * 16 + g;
            int r1 = r0 + 8;
            if (r0 < M) {
                __half2 h = __floats2half2_rn(acc[mt][nt][0] + b0v, acc[mt][nt][1] + b1v);
                *reinterpret_cast<__half2*>(&C[(size_t)r0 * ldc + sl.cofs + lc]) = h;
            }
            if (r1 < M) {
                __half2 h = __floats2half2_rn(acc[mt][nt][2] + b0v, acc[mt][nt][3] + b1v);
                *reinterpret_cast<__half2*>(&C[(size_t)r1 * ldc + sl.cofs + lc]) = h;
            }
        }
    }
}

// ---------------- attention: fused 320B rows, uniform chunk mapping ----------
// Per edge: 3 fused rows (v/r/t), each 20 x 16B chunks -> 60 chunks over
// 32 lanes x 2 slots (slot0 = chunk l, slot1 = chunk l+32; lanes 28-31 slot1 idle).
// Chunk idx<16: K channels idx*8..+7 (head = idx<8 ? 0 : 1). idx>=16: CV sub idx-16.
__global__ __launch_bounds__(128)
void tgn_attn(const int* __restrict__ node, const int* __restrict__ nbr,
              const void* __restrict__ maskp,
              const float* __restrict__ bc,
              float* __restrict__ out, int N)
{
    int i = blockIdx.x;
    if (i >= N) return;
    int tid = threadIdx.x, w = tid >> 5, l = tid & 31;
    __shared__ float sAcc[4][12][8];
    __shared__ int   sUnm[4];

    int v, tq;
    if (g_is64) { v = node[i * 8 + 0]; tq = node[i * 8 + 4]; }
    else        { v = node[i * 4 + 0]; tq = node[i * 4 + 2]; }

    const int*           maski = (const int*)maskp;
    const unsigned char* maskb = (const unsigned char*)maskp;
    int m32 = g_mask32;

    // chunk meta (static per lane)
    int  c0 = l,       t0 = c0 / 20, i0 = c0 - t0 * 20;
    int  c1 = l + 32;
    bool has1 = (c1 < 60);
    int  t1 = c1 / 20, i1 = c1 - t1 * 20;
    bool k0 = (i0 < 16);
    bool k1 = has1 && (i1 < 16);
    bool cvA = (i0 >= 16);
    bool cvB = has1 && (i1 >= 16);
    int  cv0 = i0 - 16, cv1 = i1 - 16;

    // edge tuples + row pointers for this warp's 5 edges
    const __half* bpA[5];
    const __half* bpB[5];
    int mk[5];
#pragma unroll
    for (int s = 0; s < 5; ++s) {
        int j  = w + s * 4;
        int eb = (i * NBRS + j) * 3;
        int nv = nbr[eb], nr = nbr[eb + 1], nt = nbr[eb + 2];
        mk[s]  = m32 ? maski[i * NBRS + j] : (int)maskb[i * NBRS + j];
        int di = tq - nt + DT_OFF;
        di = min(max(di, 0), DT_ROWS - 1);
        const __half* bv = &g_tabFv[(size_t)nv * ROWH];
        const __half* br = &g_tabFr[(size_t)nr * ROWH];
        const __half* bt = &g_tabFt[(size_t)di * ROWH];
        bpA[s] = (t0 == 0) ? bv : (t0 == 1) ? br : bt;
        bpB[s] = (t1 == 0) ? bv : (t1 == 1) ? br : bt;
    }

    // prefetch: up to 10 independent LDG.128 per lane
    uint4 bufA[5], bufB[5];
#pragma unroll
    for (int s = 0; s < 5; ++s) {
        bufA[s] = *reinterpret_cast<const uint4*>(bpA[s] + i0 * 8);
        if (has1) bufB[s] = *reinterpret_cast<const uint4*>(bpB[s] + i1 * 8);
    }

    // q fragments for held K chunks
    float qfA[8] = {0,0,0,0,0,0,0,0}, qfB[8] = {0,0,0,0,0,0,0,0};
    if (k0) {
        uint4 qv = *reinterpret_cast<const uint4*>(&g_tabQ_h[(size_t)v * 128 + i0 * 8]);
        __half2* qh = reinterpret_cast<__half2*>(&qv);
#pragma unroll
        for (int j = 0; j < 4; ++j) {
            float2 f = __half22float2(qh[j]);
            qfA[2 * j] = f.x; qfA[2 * j + 1] = f.y;
        }
    }
    if (k1) {
        uint4 qv = *reinterpret_cast<const uint4*>(&g_tabQ_h[(size_t)v * 128 + i1 * 8]);
        __half2* qh = reinterpret_cast<__half2*>(&qv);
#pragma unroll
        for (int j = 0; j < 4; ++j) {
            float2 f = __half22float2(qh[j]);
            qfB[2 * j] = f.x; qfB[2 * j + 1] = f.y;
        }
    }

    float accA[8] = {0,0,0,0,0,0,0,0}, accB[8] = {0,0,0,0,0,0,0,0};
    int unm = 0;

#pragma unroll
    for (int s = 0; s < 5; ++s) {
        float fA[8], fB[8];
        {
            __half2* h = reinterpret_cast<__half2*>(&bufA[s]);
#pragma unroll
            for (int j = 0; j < 4; ++j) {
                float2 f = __half22float2(h[j]);
                fA[2 * j] = f.x; fA[2 * j + 1] = f.y;
            }
        }
        if (has1) {
            __half2* h = reinterpret_cast<__half2*>(&bufB[s]);
#pragma unroll
            for (int j = 0; j < 4; ++j) {
                float2 f = __half22float2(h[j]);
                fB[2 * j] = f.x; fB[2 * j + 1] = f.y;
            }
        }

        float sp0 = 0.f, sp1 = 0.f;
        if (k0) {
            float d = qfA[0]*fA[0] + qfA[1]*fA[1] + qfA[2]*fA[2] + qfA[3]*fA[3]
                    + qfA[4]*fA[4] + qfA[5]*fA[5] + qfA[6]*fA[6] + qfA[7]*fA[7];
            if (i0 < 8) sp0 += d; else sp1 += d;
        }
        if (k1) {
            float d = qfB[0]*fB[0] + qfB[1]*fB[1] + qfB[2]*fB[2] + qfB[3]*fB[3]
                    + qfB[4]*fB[4] + qfB[5]*fB[5] + qfB[6]*fB[6] + qfB[7]*fB[7];
            if (i1 < 8) sp0 += d; else sp1 += d;
        }
#pragma unroll
        for (int off = 16; off; off >>= 1) {
            sp0 += __shfl_xor_sync(0xffffffffu, sp0, off);
            sp1 += __shfl_xor_sync(0xffffffffu, sp1, off);
        }
        float a0, a1;
        if (mk[s]) { a0 = 0.5f; a1 = 0.5f; }
        else {
            const float sc = 0.08838834764831843f;    // 1/sqrt(128)
            float s0 = sp0 * sc, s1 = sp1 * sc;
            float mx = fmaxf(s0, s1);
            float e0 = expf(s0 - mx), e1 = expf(s1 - mx);
            float inv = 1.0f / (e0 + e1);
            a0 = e0 * inv; a1 = e1 * inv;
            unm++;
        }
        if (cvA) {
            float a = (cv0 < 2) ? a0 : a1;
#pragma unroll
            for (int j = 0; j < 8; ++j) accA[j] += a * fA[j];
        }
        if (cvB) {
            float a = (cv1 < 2) ? a0 : a1;
#pragma unroll
            for (int j = 0; j < 8; ++j) accB[j] += a * fB[j];
        }
    }

    if (cvA) {
#pragma unroll
        for (int j = 0; j < 8; ++j) sAcc[w][t0 * 4 + cv0][j] = accA[j];
    }
    if (cvB) {
#pragma unroll
        for (int j = 0; j < 8; ++j) sAcc[w][t1 * 4 + cv1][j] = accB[j];
    }
    if (l == 0) sUnm[w] = unm;
    __syncthreads();

    if (tid < NCLS) {
        int c = tid, hsub = c >> 3, ch = c & 7;
        float v0 = 0.f, v1 = 0.f;
#pragma unroll
        for (int w4 = 0; w4 < 4; ++w4)
#pragma unroll
            for (int t3 = 0; t3 < 3; ++t3) {
                v0 += sAcc[w4][t3 * 4 + hsub][ch];
                v1 += sAcc[w4][t3 * 4 + 2 + hsub][ch];
            }
        int tot = sUnm[0] + sUnm[1] + sUnm[2] + sUnm[3];
        out[(size_t)i * NCLS + c] = (tot == 0) ? bc[c] : (g_bco[c] + v0 + v1);
    }
}

// ---------------- launch ------------------------------------------------------
extern "C" void kernel_launch(void* const* d_in, const int* in_sizes, int n_in,
                              void* d_out, int out_size)
{
    const int*   node  = (const int*)d_in[0];
    const int*   nbr   = (const int*)d_in[1];
    const void*  mask  = d_in[2];
    const float* v_emb = (const float*)d_in[3];
    const float* r_emb = (const float*)d_in[4];
    const float* tw    = (const float*)d_in[5];
    const float* tb    = (const float*)d_in[6];
    const float* Wq    = (const float*)d_in[7];
    const float* bq    = (const float*)d_in[8];
    const float* Wk    = (const float*)d_in[9];
    const float* bk    = (const float*)d_in[10];
    const float* Wv    = (const float*)d_in[11];
    const float* bv    = (const float*)d_in[12];
    const float* Wo    = (const float*)d_in[13];
    const float* bo    = (const float*)d_in[14];
    const float* Wc    = (const float*)d_in[15];
    const float* bc    = (const float*)d_in[16];
    float* out = (float*)d_out;

    int N  = in_sizes[0] / 4;
    int Mv = in_sizes[3] / 128;
    int Mr = in_sizes[4] / 128;

    tgn_detect_node<<<1, 256>>>(node, in_sizes[0]);
    tgn_detect_mask<<<1, 256>>>((const unsigned char*)mask, in_sizes[2]);

    tgn_prep<<<1, 128>>>(Wq, bq, Wv, bv, Wo, bo, Wc, bc, tb);

    tgn_cosE<<<(int)(((long)DT_ROWS * 32 + 255) / 256), 256>>>(tw, tb);

    TSlice3 Pv;                    // v_emb: Q, Fv-K, Fv-CV
    Pv.s[0] = { Wq,       nullptr, 256, 0,   0, 128, 1, 0 };
    Pv.s[1] = { Wk,       nullptr, 384, 1,   0, 128, 0, 0 };
    Pv.s[2] = { nullptr,  nullptr, 128, 1, 128,  32, 0, 1 };
    tgn_mma<<<dim3((Mv + 127) / 128, 3), 256>>>(v_emb, Mv, Pv);

    TSlice3 Pr;                    // r_emb: Fr-K, Fr-CV
    Pr.s[0] = { Wk + 128, nullptr, 384, 2,   0, 128, 0, 0 };
    Pr.s[1] = { nullptr,  nullptr, 128, 2, 128,  32, 0, 2 };
    Pr.s[2] = Pr.s[0];
    tgn_mma<<<dim3((Mr + 127) / 128, 2), 256>>>(r_emb, Mr, Pr);

    TSlice3 Pt;                    // E: Ft-K (+bk), Ft-CV (+cvb)
    Pt.s[0] = { Wk + 256, bk,      384, 3,   0, 128, 0, 0 };
    Pt.s[1] = { nullptr,  nullptr, 128, 3, 128,  32, 2, 3 };
    Pt.s[2] = Pt.s[0];
    tgn_mma<<<dim3((DT_ROWS + 127) / 128, 2), 256>>>(nullptr, DT_ROWS, Pt);

    tgn_attn<<<N, 128>>>(node, nbr, mask, bc, out, N);
}

// round 15
// speedup vs baseline: 1.0650x; 1.0650x over previous
#include <cuda_runtime.h>
#include <cuda_fp16.h>
#include <cstdint>
#include <math.h>

#define V_NUM   100000
#define R_NUM   100000
#define NBRS    20
#define NCLS    10
#define DT_ROWS 200004
#define DT_OFF  100000

// ---------------- scratch tables (device globals) ---------------------------
__device__ __align__(16) __half g_tabQ_h  [(size_t)V_NUM * 128];   //  25.6 MB
__device__ __align__(16) __half g_tabKVv_h[(size_t)V_NUM * 256];   //  51.2 MB
__device__ __align__(16) __half g_tabKVr_h[(size_t)R_NUM * 256];   //  51.2 MB
__device__ __align__(16) __half g_tabKVt_h[(size_t)DT_ROWS * 256]; // 102.4 MB
__device__ __align__(16) float  g_E       [(size_t)DT_ROWS * 128]; // 102.4 MB cos matrix
__device__ float g_qcb [128];
__device__ float g_Wco [NCLS * 128];              // Wc @ Wo
__device__ float g_bco [NCLS];                    // Wc @ bo + bc
__device__ int   g_is64;
__device__ int   g_mask32;

// Fast fp32 cosine with FMA Cody-Waite reduction (no DP, fast-math-proof).
__device__ __forceinline__ float cosq(float x)
{
    float kf = rintf(x * 0.6366197723675814f);
    int   k  = (int)kf;
    float r  = fmaf(kf, -1.57079637050628662109375f, x);
    r        = fmaf(kf,  4.37113900018624283e-8f,    r);
    float r2 = r * r;
    float c = fmaf(r2, fmaf(r2, fmaf(r2, fmaf(r2, 2.47959626e-5f, -1.38888876e-3f),
                                      4.16666418e-2f), -4.99999970e-1f), 1.0f);
    float s = r * fmaf(r2, fmaf(r2, fmaf(r2, -1.95152959e-4f, 8.33216087e-3f),
                                 -1.66666546e-1f), 1.0f);
    int q = k & 3;
    float res = (q & 1) ? s : c;
    return ((q == 1) || (q == 2)) ? -res : res;
}

__device__ __forceinline__ uint32_t f2tf32(float f)
{
    uint32_t u;
    asm("cvt.rna.tf32.f32 %0, %1;" : "=r"(u) : "f"(f));
    return u;
}

__device__ __forceinline__ void mma8(float* d, const uint32_t* a, uint32_t b0, uint32_t b1)
{
    asm volatile(
        "mma.sync.aligned.m16n8k8.row.col.f32.tf32.tf32.f32 "
        "{%0,%1,%2,%3},{%4,%5,%6,%7},{%8,%9},{%0,%1,%2,%3};"
        : "+f"(d[0]), "+f"(d[1]), "+f"(d[2]), "+f"(d[3])
        : "r"(a[0]), "r"(a[1]), "r"(a[2]), "r"(a[3]), "r"(b0), "r"(b1));
}

// ---------------- dtype detects ----------------------------------------------
__global__ void tgn_detect_node(const int* __restrict__ node, int n_words)
{
    __shared__ int sOr[256];
    int t = threadIdx.x;
    int acc = 0;
    for (int i = 1 + 2 * t; i < n_words; i += 512) acc |= node[i];
    sOr[t] = acc;
    __syncthreads();
    for (int s = 128; s; s >>= 1) { if (t < s) sOr[t] |= sOr[t + s]; __syncthreads(); }
    if (t == 0) g_is64 = (sOr[0] == 0) ? 1 : 0;
}

__global__ void tgn_detect_mask(const unsigned char* __restrict__ m, int n_elems)
{
    __shared__ int sOr[256];
    int t = threadIdx.x;
    int acc = 0;
    for (int i = t; i < n_elems; i += 256)
        if (i & 3) acc |= m[i];
    sOr[t] = acc;
    __syncthreads();
    for (int s = 128; s; s >>= 1) { if (t < s) sOr[t] |= sOr[t + s]; __syncthreads(); }
    if (t == 0) g_mask32 = (sOr[0] == 0) ? 1 : 0;
}

// ---------------- prep: small constants --------------------------------------
__global__ void tgn_prep(const float* __restrict__ Wq, const float* __restrict__ bq,
                         const float* __restrict__ Wo, const float* __restrict__ bo,
                         const float* __restrict__ Wc, const float* __restrict__ bc,
                         const float* __restrict__ tb)
{
    int t = threadIdx.x;  // 128 threads
    float acc = bq[t];
    for (int c = 0; c < 128; ++c) acc += Wq[t * 256 + 128 + c] * cosq(tb[c]);
    g_qcb[t] = acc;
    for (int c = 0; c < NCLS; ++c) {
        float s = 0.f;
        for (int m = 0; m < 128; ++m) s += Wc[c * 128 + m] * Wo[m * 128 + t];
        g_Wco[c * 128 + t] = s;
    }
    if (t < NCLS) {
        float s = bc[t];
        for (int m = 0; m < 128; ++m) s += Wc[t * 128 + m] * bo[m];
        g_bco[t] = s;
    }
}

// ---------------- cos matrix E[dt][c] = cos(d*w_c + b_c), 4 chans/thread -----
__global__ void tgn_cosE(const float* __restrict__ tw, const float* __restrict__ tb)
{
    long idx = (long)blockIdx.x * 256 + threadIdx.x;
    long row = idx >> 5;
    if (row >= DT_ROWS) return;
    int  c4 = (int)(idx & 31) * 4;
    float dv = (float)(row - DT_OFF);
    float4 w = *reinterpret_cast<const float4*>(&tw[c4]);
    float4 b = *reinterpret_cast<const float4*>(&tb[c4]);
    float4 o;
    o.x = cosq(__fadd_rn(__fmul_rn(dv, w.x), b.x));
    o.y = cosq(__fadd_rn(__fmul_rn(dv, w.y), b.y));
    o.z = cosq(__fadd_rn(__fmul_rn(dv, w.z), b.z));
    o.w = cosq(__fadd_rn(__fmul_rn(dv, w.w), b.w));
    *reinterpret_cast<float4*>(&g_E[row * 128 + c4]) = o;
}

// ---------------- unified tf32 MMA table GEMM --------------------------------
struct TSlice  { const float* W; const float* bias; int ldw; int tab; int ldc; int cofs; int qcb; };
struct TSlice3 { TSlice s[3]; };

__global__ __launch_bounds__(256)
void tgn_mma(const float* __restrict__ Ain, int M, TSlice3 P)
{
    __shared__ uint32_t As[128][36];
    __shared__ uint32_t Bs[128][36];
    TSlice sl = P.s[blockIdx.y];
    const float* A = Ain ? Ain : (const float*)g_E;
    __half* C = (sl.tab == 0) ? g_tabQ_h : (sl.tab == 1) ? g_tabKVv_h
              : (sl.tab == 2) ? g_tabKVr_h : g_tabKVt_h;
    const float* bias = sl.qcb ? g_qcb : sl.bias;

    int m0   = blockIdx.x * 128;
    int tid  = threadIdx.x;
    int warp = tid >> 5, lane = tid & 31;
    int wm = warp >> 2, wn = warp & 3;
    int g  = lane >> 2, t4 = lane & 3;

    float acc[4][4][4];
#pragma unroll
    for (int a = 0; a < 4; ++a)
#pragma unroll
        for (int b = 0; b < 4; ++b)
#pragma unroll
            for (int d = 0; d < 4; ++d) acc[a][b][d] = 0.f;

    for (int kc = 0; kc < 128; kc += 32) {
        __syncthreads();
#pragma unroll
        for (int it = 0; it < 4; ++it) {
            int idx = tid + it * 256;
            int r   = idx >> 3;
            int c4  = (idx & 7) * 4;
            float4 av = make_float4(0.f, 0.f, 0.f, 0.f);
            if (m0 + r < M)
                av = *reinterpret_cast<const float4*>(&A[(size_t)(m0 + r) * 128 + kc + c4]);
            As[r][c4 + 0] = f2tf32(av.x); As[r][c4 + 1] = f2tf32(av.y);
            As[r][c4 + 2] = f2tf32(av.z); As[r][c4 + 3] = f2tf32(av.w);
            float4 bv = *reinterpret_cast<const float4*>(&sl.W[(size_t)r * sl.ldw + kc + c4]);
            Bs[r][c4 + 0] = f2tf32(bv.x); Bs[r][c4 + 1] = f2tf32(bv.y);
            Bs[r][c4 + 2] = f2tf32(bv.z); Bs[r][c4 + 3] = f2tf32(bv.w);
        }
        __syncthreads();
#pragma unroll
        for (int ks = 0; ks < 4; ++ks) {
            int k0 = ks * 8;
            uint32_t af[4][4];
#pragma unroll
            for (int mt = 0; mt < 4; ++mt) {
                int rm = wm * 64 + mt * 16;
                af[mt][0] = As[rm + g    ][k0 + t4];
                af[mt][1] = As[rm + g + 8][k0 + t4];
                af[mt][2] = As[rm + g    ][k0 + t4 + 4];
                af[mt][3] = As[rm + g + 8][k0 + t4 + 4];
            }
#pragma unroll
            for (int nt = 0; nt < 4; ++nt) {
                int nb = wn * 32 + nt * 8;
                uint32_t b0 = Bs[nb + g][k0 + t4];
                uint32_t b1 = Bs[nb + g][k0 + t4 + 4];
#pragma unroll
                for (int mt = 0; mt < 4; ++mt)
                    mma8(acc[mt][nt], af[mt], b0, b1);
            }
        }
    }

#pragma unroll
    for (int nt = 0; nt < 4; ++nt) {
        int lc = wn * 32 + nt * 8 + 2 * t4;
        float b0v = bias ? bias[lc]     : 0.f;
        float b1v = bias ? bias[lc + 1] : 0.f;
#pragma unroll
        for (int mt = 0; mt < 4; ++mt) {
            int r0 = m0 + wm * 64 + mt * 16 + g;
            int r1 = r0 + 8;
            if (r0 < M) {
                __half2 h = __floats2half2_rn(acc[mt][nt][0] + b0v, acc[mt][nt][1] + b1v);
                *reinterpret_cast<__half2*>(&C[(size_t)r0 * sl.ldc + sl.cofs + lc]) = h;
            }
            if (r1 < M) {
                __half2 h = __floats2half2_rn(acc[mt][nt][2] + b0v, acc[mt][nt][3] + b1v);
                *reinterpret_cast<__half2*>(&C[(size_t)r1 * sl.ldc + sl.cofs + lc]) = h;
            }
        }
    }
}

// ---------------- attention: WARP-PER-NODE, depth-4 pipelined gathers --------
// Row layout (512B): chunks 0-15 = K ch 8c..8c+7 (head0 = chunks 0-7), 16-31 = V.
// Lane l owns chunk l of each gathered row. 8 nodes per 256-thread block.
__global__ __launch_bounds__(256)
void tgn_attn(const int* __restrict__ node, const int* __restrict__ nbr,
              const void* __restrict__ maskp,
              const float* __restrict__ bc,
              float* __restrict__ out, int N)
{
    int tid = threadIdx.x, w = tid >> 5, l = tid & 31;
    int i = blockIdx.x * 8 + w;
    __shared__ float sF[8][128];
    if (i >= N) return;

    int v, tq;
    if (g_is64) { v = node[i * 8 + 0]; tq = node[i * 8 + 4]; }
    else        { v = node[i * 4 + 0]; tq = node[i * 4 + 2]; }

    const int*           maski = (const int*)maskp;
    const unsigned char* maskb = (const unsigned char*)maskp;
    int m32 = g_mask32;

    // q fragment: lanes 0-15 hold channels 8l..8l+7
    float qf[8] = {0.f, 0.f, 0.f, 0.f, 0.f, 0.f, 0.f, 0.f};
    if (l < 16) {
        uint4 qv = *reinterpret_cast<const uint4*>(&g_tabQ_h[(size_t)v * 128 + l * 8]);
        __half2* qh = reinterpret_cast<__half2*>(&qv);
#pragma unroll
        for (int j = 0; j < 4; ++j) {
            float2 f = __half22float2(qh[j]);
            qf[2 * j] = f.x; qf[2 * j + 1] = f.y;
        }
    }

    uint4 bv[4], br[4], bt[4];
    int   mk[4];

#define STAGE(j, slot)                                                                       \
    {                                                                                        \
        int eb = (i * NBRS + (j)) * 3;                                                       \
        int nv = nbr[eb], nr = nbr[eb + 1], nt = nbr[eb + 2];                                \
        mk[slot] = m32 ? maski[i * NBRS + (j)] : (int)maskb[i * NBRS + (j)];                 \
        int di = tq - nt + DT_OFF;                                                           \
        di = min(max(di, 0), DT_ROWS - 1);                                                   \
        bv[slot] = *reinterpret_cast<const uint4*>(&g_tabKVv_h[(size_t)nv * 256 + l * 8]);   \
        br[slot] = *reinterpret_cast<const uint4*>(&g_tabKVr_h[(size_t)nr * 256 + l * 8]);   \
        bt[slot] = *reinterpret_cast<const uint4*>(&g_tabKVt_h[(size_t)di * 256 + l * 8]);   \
    }

    STAGE(0, 0); STAGE(1, 1); STAGE(2, 2); STAGE(3, 3);

    float o[8] = {0.f, 0.f, 0.f, 0.f, 0.f, 0.f, 0.f, 0.f};
    int unm = 0;

#pragma unroll
    for (int j = 0; j < NBRS; ++j) {
        int slot = j & 3;
        float f3[8];
        {
            __half2* hv = reinterpret_cast<__half2*>(&bv[slot]);
            __half2* hr = reinterpret_cast<__half2*>(&br[slot]);
            __half2* ht = reinterpret_cast<__half2*>(&bt[slot]);
#pragma unroll
            for (int q = 0; q < 4; ++q) {
                float2 a = __half22float2(hv[q]);
                float2 b = __half22float2(hr[q]);
                float2 c = __half22float2(ht[q]);
                f3[2 * q]     = a.x + b.x + c.x;
                f3[2 * q + 1] = a.y + b.y + c.y;
            }
        }
        int mcur = mk[slot];
        if (j + 4 < NBRS) STAGE(j + 4, slot);       // refill the slot just consumed

        // score partials on K lanes (V lanes have qf = 0)
        float sp = qf[0]*f3[0] + qf[1]*f3[1] + qf[2]*f3[2] + qf[3]*f3[3]
                 + qf[4]*f3[4] + qf[5]*f3[5] + qf[6]*f3[6] + qf[7]*f3[7];
        sp += __shfl_xor_sync(0xffffffffu, sp, 1);
        sp += __shfl_xor_sync(0xffffffffu, sp, 2);
        sp += __shfl_xor_sync(0xffffffffu, sp, 4);
        float p0 = __shfl_sync(0xffffffffu, sp, 0);   // head 0 score * sqrt(128)
        float p1 = __shfl_sync(0xffffffffu, sp, 8);   // head 1
        float a0, a1;
        if (mcur) { a0 = 0.5f; a1 = 0.5f; }
        else {
            const float sc = 0.08838834764831843f;    // 1/sqrt(128)
            float s0 = p0 * sc, s1 = p1 * sc;
            float mx = fmaxf(s0, s1);
            float e0 = expf(s0 - mx), e1 = expf(s1 - mx);
            float inv = 1.0f / (e0 + e1);
            a0 = e0 * inv; a1 = e1 * inv;
            unm++;
        }
        float a = (l < 24) ? a0 : a1;                 // V head0 = lanes 16-23
#pragma unroll
        for (int c = 0; c < 8; ++c) o[c] += a * f3[c];
    }
#undef STAGE

    if (l >= 16) {
#pragma unroll
        for (int c = 0; c < 8; ++c) sF[w][(l - 16) * 8 + c] = o[c];
    }
    __syncwarp();

    if (l < NCLS) {
        const float* wr = &g_Wco[l * 128];
        float acc = 0.f;
#pragma unroll 8
        for (int c = 0; c < 128; c += 4) {
            float4 wv = *reinterpret_cast<const float4*>(&wr[c]);
            float4 fv = *reinterpret_cast<const float4*>(&sF[w][c]);
            acc += wv.x * fv.x + wv.y * fv.y + wv.z * fv.z + wv.w * fv.w;
        }
        out[(size_t)i * NCLS + l] = (unm == 0) ? bc[l] : (g_bco[l] + acc);
    }
}

// ---------------- launch ------------------------------------------------------
extern "C" void kernel_launch(void* const* d_in, const int* in_sizes, int n_in,
                              void* d_out, int out_size)
{
    const int*   node  = (const int*)d_in[0];
    const int*   nbr   = (const int*)d_in[1];
    const void*  mask  = d_in[2];
    const float* v_emb = (const float*)d_in[3];
    const float* r_emb = (const float*)d_in[4];
    const float* tw    = (const float*)d_in[5];
    const float* tb    = (const float*)d_in[6];
    const float* Wq    = (const float*)d_in[7];
    const float* bq    = (const float*)d_in[8];
    const float* Wk    = (const float*)d_in[9];
    const float* bk    = (const float*)d_in[10];
    const float* Wv    = (const float*)d_in[11];
    const float* bv    = (const float*)d_in[12];
    const float* Wo    = (const float*)d_in[13];
    const float* bo    = (const float*)d_in[14];
    const float* Wc    = (const float*)d_in[15];
    const float* bc    = (const float*)d_in[16];
    float* out = (float*)d_out;

    int N  = in_sizes[0] / 4;
    int Mv = in_sizes[3] / 128;
    int Mr = in_sizes[4] / 128;

    tgn_detect_node<<<1, 256>>>(node, in_sizes[0]);
    tgn_detect_mask<<<1, 256>>>((const unsigned char*)mask, in_sizes[2]);

    tgn_prep<<<1, 128>>>(Wq, bq, Wo, bo, Wc, bc, tb);

    tgn_cosE<<<(int)(((long)DT_ROWS * 32 + 255) / 256), 256>>>(tw, tb);

    TSlice3 Pv;
    Pv.s[0] = { Wq,       nullptr, 256, 0, 128,   0, 1 };
    Pv.s[1] = { Wk,       nullptr, 384, 1, 256,   0, 0 };
    Pv.s[2] = { Wv,       nullptr, 384, 1, 256, 128, 0 };
    tgn_mma<<<dim3((Mv + 127) / 128, 3), 256>>>(v_emb, Mv, Pv);

    TSlice3 Pr;
    Pr.s[0] = { Wk + 128, nullptr, 384, 2, 256,   0, 0 };
    Pr.s[1] = { Wv + 128, nullptr, 384, 2, 256, 128, 0 };
    Pr.s[2] = Pr.s[0];
    tgn_mma<<<dim3((Mr + 127) / 128, 2), 256>>>(r_emb, Mr, Pr);

    TSlice3 Pt;
    Pt.s[0] = { Wk + 256, bk,      384, 3, 256,   0, 0 };
    Pt.s[1] = { Wv + 256, bv,      384, 3, 256, 128, 0 };
    Pt.s[2] = Pt.s[0];
    tgn_mma<<<dim3((DT_ROWS + 127) / 128, 2), 256>>>(nullptr, DT_ROWS, Pt);

    tgn_attn<<<(N + 7) / 8, 256>>>(node, nbr, mask, bc, out, N);
}